// round 3
// baseline (speedup 1.0000x reference)
#include <cuda_runtime.h>
#include <math.h>

#define BS 8
#define CC 256
#define NN 1500
#define HH 8
#define DK 32

// ---------------- scratch (static device globals; no allocs) ----------------
__device__ float g_q[(size_t)BS * HH * NN * DK];           // [b][h][n][d]
__device__ float g_k[(size_t)BS * HH * NN * DK];
__device__ float g_v[(size_t)BS * HH * NN * DK];
__device__ float g_val[(size_t)BS * NN * CC];              // [b][n][c]
__device__ unsigned short g_nbr[(size_t)BS * NN * NN];     // per-row neighbor j lists
__device__ int g_cnt[BS * NN];

// ---------------- 1) mask + neighbor-list build (per batch, head-shared) ----
__global__ __launch_bounds__(256) void mask_kernel(const float* __restrict__ boxes,
                                                   const float* __restrict__ cm) {
    __shared__ float sx1[NN], sy1[NN], sx2[NN], sy2[NN], sa[NN], scm[NN];
    int b = blockIdx.y;
    const float4* bb = (const float4*)(boxes + (size_t)b * NN * 4);
    for (int idx = threadIdx.x; idx < NN; idx += blockDim.x) {
        float4 bx = bb[idx];                  // cx, cy, w, h
        float x1 = bx.x - 0.5f * bx.z;
        float x2 = bx.x + 0.5f * bx.z;
        float y1 = bx.y - 0.5f * bx.w;
        float y2 = bx.y + 0.5f * bx.w;
        sx1[idx] = x1; sx2[idx] = x2; sy1[idx] = y1; sy2[idx] = y2;
        sa[idx] = (x2 - x1) * (y2 - y1);
        scm[idx] = cm[(size_t)b * NN + idx];
    }
    __syncthreads();

    int warp = threadIdx.x >> 5, lane = threadIdx.x & 31;
    int i = blockIdx.x * 8 + warp;
    if (i >= NN) return;
    float x1i = sx1[i], x2i = sx2[i], y1i = sy1[i], y2i = sy2[i];
    float ai = sa[i], cmi = scm[i];
    unsigned short* out = g_nbr + ((size_t)b * NN + i) * NN;
    int cnt = 0;
    for (int jb = 0; jb < NN; jb += 32) {
        int j = jb + lane;
        bool nb = false;
        if (j < NN) {
            float ltx = fmaxf(x1i, sx1[j]);
            float lty = fmaxf(y1i, sy1[j]);
            float rbx = fminf(x2i, sx2[j]);
            float rby = fminf(y2i, sy2[j]);
            float iw = fmaxf(rbx - ltx, 0.0f);
            float ih = fmaxf(rby - lty, 0.0f);
            float inter = iw * ih;
            float uni = (ai + sa[j]) - inter;
            float iou = __fdiv_rn(inter, uni);     // IEEE RN regardless of fast-math
            float t = iou * cmi * scm[j];          // NaN -> compare false, as in ref
            nb = t > 0.5f;
        }
        unsigned bal = __ballot_sync(0xffffffffu, nb);
        int pos = cnt + __popc(bal & ((1u << lane) - 1u));
        if (nb) out[pos] = (unsigned short)j;
        cnt += __popc(bal);
    }
    if (lane == 0) g_cnt[b * NN + i] = cnt;
}

// ---------------- 2) QKV head projections -----------------------------------
__global__ __launch_bounds__(256) void qkv_kernel(const float* __restrict__ qin,
                                                  const float* __restrict__ kin,
                                                  const float* __restrict__ vin,
                                                  const float* __restrict__ wq,
                                                  const float* __restrict__ wk,
                                                  const float* __restrict__ wv) {
    __shared__ float4 sw[256];   // 32x32 weight matrix for this (mat, h)
    int mat = blockIdx.z;
    int bh = blockIdx.y;
    int b = bh >> 3, h = bh & 7;
    const float* W = (mat == 0 ? wq : (mat == 1 ? wk : wv)) + h * DK * DK;
    const float* X = (mat == 0 ? qin : (mat == 1 ? kin : vin));
    float* O = (mat == 0 ? g_q : (mat == 1 ? g_k : g_v));
    sw[threadIdx.x] = ((const float4*)W)[threadIdx.x];
    __syncthreads();

    int i = blockIdx.x * 256 + threadIdx.x;
    if (i >= NN) return;
    float x[DK];
    const float* xp = X + ((size_t)b * CC + h * DK) * NN + i;
#pragma unroll
    for (int j = 0; j < DK; j++) x[j] = xp[(size_t)j * NN];

    float out[DK];
#pragma unroll
    for (int d = 0; d < DK; d++) {
        float acc = 0.0f;
#pragma unroll
        for (int jq = 0; jq < 8; jq++) {
            float4 w4 = sw[d * 8 + jq];
            acc = fmaf(w4.x, x[jq * 4 + 0], acc);
            acc = fmaf(w4.y, x[jq * 4 + 1], acc);
            acc = fmaf(w4.z, x[jq * 4 + 2], acc);
            acc = fmaf(w4.w, x[jq * 4 + 3], acc);
        }
        out[d] = acc;
    }
    float4* op = (float4*)(O + ((size_t)bh * NN + i) * DK);
#pragma unroll
    for (int r = 0; r < 8; r++)
        op[r] = make_float4(out[r * 4], out[r * 4 + 1], out[r * 4 + 2], out[r * 4 + 3]);
}

// ---------------- 3) sparse masked attention (warp per query) ---------------
// Warp = 8 neighbor-groups (g=lane>>2) x 4 d-chunks (c=lane&3, 8 floats each).
// Each group keeps an independent online-softmax stream (m,l,o); streams are
// merged once at the end. Dot product needs only 2 shfls; no per-iteration
// cross-group max broadcast -> short serial chain per 8 neighbors.
__global__ __launch_bounds__(256) void attn_kernel() {
    int warp = threadIdx.x >> 5, lane = threadIdx.x & 31;
    int g = lane >> 2, c = lane & 3;
    int bh = blockIdx.y;
    int b = bh >> 3;
    int i = blockIdx.x * 8 + warp;
    if (i >= NN) return;

    int cnt = g_cnt[b * NN + i];
    float* valp = g_val + ((size_t)b * NN + i) * CC + (bh & 7) * DK;
    const float* vb = g_v + (size_t)bh * NN * DK;
    if (cnt == 0) {   // has_nb == 0 fallback: val = v
        if (g == 0) {
            float4 va = ((const float4*)(vb + (size_t)i * DK))[c * 2];
            float4 vbb = ((const float4*)(vb + (size_t)i * DK))[c * 2 + 1];
            ((float4*)valp)[c * 2] = va;
            ((float4*)valp)[c * 2 + 1] = vbb;
        }
        return;
    }

    const float4* qp = (const float4*)(g_q + ((size_t)bh * NN + i) * DK);
    float4 qa = qp[c * 2], qb = qp[c * 2 + 1];
    const unsigned short* nb = g_nbr + ((size_t)b * NN + i) * NN;
    const float* kb = g_k + (size_t)bh * NN * DK;
    int cm1 = cnt - 1;

    // reference: max_val = max(attn * mask) -> masked zeros participate in max
    float m_g = (cnt < NN) ? 0.0f : -INFINITY;
    float l = 0.0f;
    float4 oa = make_float4(0.f, 0.f, 0.f, 0.f);
    float4 ob = make_float4(0.f, 0.f, 0.f, 0.f);

    // prologue: load chunk 0 (clamped indices -> always-valid loads)
    int j0 = nb[min(g, cm1)];
    float4 ka = ((const float4*)(kb + (size_t)j0 * DK))[c * 2];
    float4 kc4 = ((const float4*)(kb + (size_t)j0 * DK))[c * 2 + 1];
    float4 va = ((const float4*)(vb + (size_t)j0 * DK))[c * 2];
    float4 vc4 = ((const float4*)(vb + (size_t)j0 * DK))[c * 2 + 1];

    for (int t = 0; t < cnt; t += 8) {
        // prefetch next chunk
        int jn = nb[min(t + 8 + g, cm1)];
        float4 kna = ((const float4*)(kb + (size_t)jn * DK))[c * 2];
        float4 knb = ((const float4*)(kb + (size_t)jn * DK))[c * 2 + 1];
        float4 vna = ((const float4*)(vb + (size_t)jn * DK))[c * 2];
        float4 vnb = ((const float4*)(vb + (size_t)jn * DK))[c * 2 + 1];

        float s = qa.x * ka.x + qa.y * ka.y + qa.z * ka.z + qa.w * ka.w
                + qb.x * kc4.x + qb.y * kc4.y + qb.z * kc4.z + qb.w * kc4.w;
        s += __shfl_xor_sync(0xffffffffu, s, 1);
        s += __shfl_xor_sync(0xffffffffu, s, 2);
        if (t + g >= cnt) s = -INFINITY;
        float m_new = fmaxf(m_g, s);
        float scale = __expf(m_g - m_new);
        float p = __expf(s - m_new);          // invalid: exp(-inf)=0
        l = l * scale + p;
        oa.x = fmaf(p, va.x, oa.x * scale);
        oa.y = fmaf(p, va.y, oa.y * scale);
        oa.z = fmaf(p, va.z, oa.z * scale);
        oa.w = fmaf(p, va.w, oa.w * scale);
        ob.x = fmaf(p, vc4.x, ob.x * scale);
        ob.y = fmaf(p, vc4.y, ob.y * scale);
        ob.z = fmaf(p, vc4.z, ob.z * scale);
        ob.w = fmaf(p, vc4.w, ob.w * scale);
        m_g = m_new;
        ka = kna; kc4 = knb; va = vna; vc4 = vnb;
    }

    // merge the 8 group streams (lane bits 2,3,4)
    float m_s = m_g;
    m_s = fmaxf(m_s, __shfl_xor_sync(0xffffffffu, m_s, 4));
    m_s = fmaxf(m_s, __shfl_xor_sync(0xffffffffu, m_s, 8));
    m_s = fmaxf(m_s, __shfl_xor_sync(0xffffffffu, m_s, 16));
    float sc = __expf(m_g - m_s);
    l *= sc;
    oa.x *= sc; oa.y *= sc; oa.z *= sc; oa.w *= sc;
    ob.x *= sc; ob.y *= sc; ob.z *= sc; ob.w *= sc;
#define XRED(v) v += __shfl_xor_sync(0xffffffffu, v, 4); \
                v += __shfl_xor_sync(0xffffffffu, v, 8); \
                v += __shfl_xor_sync(0xffffffffu, v, 16);
    XRED(l)
    XRED(oa.x) XRED(oa.y) XRED(oa.z) XRED(oa.w)
    XRED(ob.x) XRED(ob.y) XRED(ob.z) XRED(ob.w)
#undef XRED
    float inv = 1.0f / (l + 1e-8f);
    if (g == 0) {
        ((float4*)valp)[c * 2] = make_float4(oa.x * inv, oa.y * inv, oa.z * inv, oa.w * inv);
        ((float4*)valp)[c * 2 + 1] = make_float4(ob.x * inv, ob.y * inv, ob.z * inv, ob.w * inv);
    }
}

// ---------------- 4) output projection  out = Wp @ val + b ------------------
// 128(co) x 64(i) tile, 128 threads, 8x8 per thread, KC=32 chunks with
// register-prefetch double buffering (global loads of chunk k+1 overlap FFMAs
// of chunk k).
#define PCO 128
#define PII 64
#define PKC 32
__global__ __launch_bounds__(128) void proj_kernel(const float* __restrict__ wp,
                                                   const float* __restrict__ bp,
                                                   float* __restrict__ out) {
    __shared__ float Ws[PKC][PCO + 4];   // [ci][co]
    __shared__ float Vs[PKC][PII + 4];   // [ci][i]
    int b = blockIdx.z;
    int coT = blockIdx.y * PCO;
    int iT = blockIdx.x * PII;
    int t = threadIdx.x;
    int tx = t & 7;                    // i group: tx*4 and tx*4+32
    int ty = t >> 3;                   // co group (0..15): ty*4 and ty*4+64
    int ci4 = (t & 7) * 4;             // load column group (0..28)
    int r0 = t >> 3;                   // load row base (0..15)

    float4 wpre[8], vpre[4];
    // prologue: load chunk kc=0 into registers
#pragma unroll
    for (int p = 0; p < 8; p++)
        wpre[p] = *(const float4*)&wp[(size_t)(coT + r0 + p * 16) * CC + ci4];
#pragma unroll
    for (int p = 0; p < 4; p++) {
        int gi = iT + r0 + p * 16;
        vpre[p] = (gi < NN) ? *(const float4*)&g_val[((size_t)b * NN + gi) * CC + ci4]
                            : make_float4(0.f, 0.f, 0.f, 0.f);
    }

    float acc[8][8] = {};

    for (int kc = 0; kc < CC; kc += PKC) {
        // commit prefetched registers to smem
#pragma unroll
        for (int p = 0; p < 8; p++) {
            int r = r0 + p * 16;
            Ws[ci4 + 0][r] = wpre[p].x; Ws[ci4 + 1][r] = wpre[p].y;
            Ws[ci4 + 2][r] = wpre[p].z; Ws[ci4 + 3][r] = wpre[p].w;
        }
#pragma unroll
        for (int p = 0; p < 4; p++) {
            int io = r0 + p * 16;
            Vs[ci4 + 0][io] = vpre[p].x; Vs[ci4 + 1][io] = vpre[p].y;
            Vs[ci4 + 2][io] = vpre[p].z; Vs[ci4 + 3][io] = vpre[p].w;
        }
        __syncthreads();

        // issue next chunk's global loads (latency hidden under FFMAs)
        if (kc + PKC < CC) {
            int kcn = kc + PKC;
#pragma unroll
            for (int p = 0; p < 8; p++)
                wpre[p] = *(const float4*)&wp[(size_t)(coT + r0 + p * 16) * CC + kcn + ci4];
#pragma unroll
            for (int p = 0; p < 4; p++) {
                int gi = iT + r0 + p * 16;
                vpre[p] = (gi < NN) ? *(const float4*)&g_val[((size_t)b * NN + gi) * CC + kcn + ci4]
                                    : make_float4(0.f, 0.f, 0.f, 0.f);
            }
        }

#pragma unroll 8
        for (int ci = 0; ci < PKC; ci++) {
            float4 w0 = *(const float4*)&Ws[ci][ty * 4];
            float4 w1 = *(const float4*)&Ws[ci][64 + ty * 4];
            float4 v0 = *(const float4*)&Vs[ci][tx * 4];
            float4 v1 = *(const float4*)&Vs[ci][32 + tx * 4];
            float wr[8] = {w0.x, w0.y, w0.z, w0.w, w1.x, w1.y, w1.z, w1.w};
            float vr[8] = {v0.x, v0.y, v0.z, v0.w, v1.x, v1.y, v1.z, v1.w};
#pragma unroll
            for (int a = 0; a < 8; a++)
#pragma unroll
                for (int e = 0; e < 8; e++)
                    acc[a][e] = fmaf(wr[a], vr[e], acc[a][e]);
        }
        __syncthreads();
    }

#pragma unroll
    for (int a = 0; a < 8; a++) {
        int co = coT + (a < 4 ? (ty * 4 + a) : (64 + ty * 4 + (a - 4)));
        float bias = bp[co];
#pragma unroll
        for (int half = 0; half < 2; half++) {
            int gi = iT + (half == 0 ? tx * 4 : 32 + tx * 4);
            int e0 = half * 4;
            if (gi < NN) {   // NN % 4 == 0, whole float4 valid
                float4 r = make_float4(acc[a][e0 + 0] + bias, acc[a][e0 + 1] + bias,
                                       acc[a][e0 + 2] + bias, acc[a][e0 + 3] + bias);
                *(float4*)&out[((size_t)b * CC + co) * NN + gi] = r;
            }
        }
    }
}

// ---------------- launch ----------------------------------------------------
extern "C" void kernel_launch(void* const* d_in, const int* in_sizes, int n_in,
                              void* d_out, int out_size) {
    const float* queries = (const float*)d_in[0];
    const float* keys    = (const float*)d_in[1];
    const float* values  = (const float*)d_in[2];
    const float* boxes   = (const float*)d_in[3];
    const float* curmask = (const float*)d_in[4];
    const float* wq      = (const float*)d_in[5];
    const float* wk      = (const float*)d_in[6];
    const float* wv      = (const float*)d_in[7];
    const float* w_proj  = (const float*)d_in[8];
    const float* b_proj  = (const float*)d_in[9];
    float* out = (float*)d_out;

    mask_kernel<<<dim3(188, BS), 256>>>(boxes, curmask);
    qkv_kernel<<<dim3(6, BS * HH, 3), 256>>>(queries, keys, values, wq, wk, wv);
    attn_kernel<<<dim3(188, BS * HH), 256>>>();
    proj_kernel<<<dim3((NN + PII - 1) / PII, CC / PCO, BS), 128>>>(w_proj, b_proj, out);
}

// round 4
// speedup vs baseline: 1.1320x; 1.1320x over previous
#include <cuda_runtime.h>
#include <math.h>

#define BS 8
#define CC 256
#define NN 1500
#define HH 8
#define DK 32

// ---------------- scratch (static device globals; no allocs) ----------------
// q/k/v stored head-interleaved: [b][n][h*DK]  (256 floats per token row)
__device__ float g_q[(size_t)BS * NN * CC];
__device__ float g_k[(size_t)BS * NN * CC];
__device__ float g_v[(size_t)BS * NN * CC];
__device__ float g_val[(size_t)BS * NN * CC];              // [b][n][c]
__device__ unsigned short g_nbr[(size_t)BS * NN * NN];     // per-row neighbor j lists
__device__ int g_cnt[BS * NN];

// ---------------- 1) mask + neighbor-list build (per batch, head-shared) ----
__global__ __launch_bounds__(256) void mask_kernel(const float* __restrict__ boxes,
                                                   const float* __restrict__ cm) {
    __shared__ float sx1[NN], sy1[NN], sx2[NN], sy2[NN], sa[NN], scm[NN];
    int b = blockIdx.y;
    const float4* bb = (const float4*)(boxes + (size_t)b * NN * 4);
    for (int idx = threadIdx.x; idx < NN; idx += blockDim.x) {
        float4 bx = bb[idx];                  // cx, cy, w, h
        float x1 = bx.x - 0.5f * bx.z;
        float x2 = bx.x + 0.5f * bx.z;
        float y1 = bx.y - 0.5f * bx.w;
        float y2 = bx.y + 0.5f * bx.w;
        sx1[idx] = x1; sx2[idx] = x2; sy1[idx] = y1; sy2[idx] = y2;
        sa[idx] = (x2 - x1) * (y2 - y1);
        scm[idx] = cm[(size_t)b * NN + idx];
    }
    __syncthreads();

    int warp = threadIdx.x >> 5, lane = threadIdx.x & 31;
    int i = blockIdx.x * 8 + warp;
    if (i >= NN) return;
    float x1i = sx1[i], x2i = sx2[i], y1i = sy1[i], y2i = sy2[i];
    float ai = sa[i], cmi = scm[i];
    unsigned short* out = g_nbr + ((size_t)b * NN + i) * NN;
    int cnt = 0;
    for (int jb = 0; jb < NN; jb += 32) {
        int j = jb + lane;
        bool nb = false;
        if (j < NN) {
            float ltx = fmaxf(x1i, sx1[j]);
            float lty = fmaxf(y1i, sy1[j]);
            float rbx = fminf(x2i, sx2[j]);
            float rby = fminf(y2i, sy2[j]);
            float iw = fmaxf(rbx - ltx, 0.0f);
            float ih = fmaxf(rby - lty, 0.0f);
            float inter = iw * ih;
            float uni = (ai + sa[j]) - inter;
            float iou = __fdiv_rn(inter, uni);     // IEEE RN regardless of fast-math
            float t = iou * cmi * scm[j];          // NaN -> compare false, as in ref
            nb = t > 0.5f;
        }
        unsigned bal = __ballot_sync(0xffffffffu, nb);
        int pos = cnt + __popc(bal & ((1u << lane) - 1u));
        if (nb) out[pos] = (unsigned short)j;
        cnt += __popc(bal);
    }
    if (lane == 0) g_cnt[b * NN + i] = cnt;
}

// ---------------- 2) QKV head projections (head-interleaved output) ---------
__global__ __launch_bounds__(256) void qkv_kernel(const float* __restrict__ qin,
                                                  const float* __restrict__ kin,
                                                  const float* __restrict__ vin,
                                                  const float* __restrict__ wq,
                                                  const float* __restrict__ wk,
                                                  const float* __restrict__ wv) {
    __shared__ float4 sw[256];   // 32x32 weight matrix for this (mat, h)
    int mat = blockIdx.z;
    int bh = blockIdx.y;
    int b = bh >> 3, h = bh & 7;
    const float* W = (mat == 0 ? wq : (mat == 1 ? wk : wv)) + h * DK * DK;
    const float* X = (mat == 0 ? qin : (mat == 1 ? kin : vin));
    float* O = (mat == 0 ? g_q : (mat == 1 ? g_k : g_v));
    sw[threadIdx.x] = ((const float4*)W)[threadIdx.x];
    __syncthreads();

    int i = blockIdx.x * 256 + threadIdx.x;
    if (i >= NN) return;
    float x[DK];
    const float* xp = X + ((size_t)b * CC + h * DK) * NN + i;
#pragma unroll
    for (int j = 0; j < DK; j++) x[j] = xp[(size_t)j * NN];

    float out[DK];
#pragma unroll
    for (int d = 0; d < DK; d++) {
        float acc = 0.0f;
#pragma unroll
        for (int jq = 0; jq < 8; jq++) {
            float4 w4 = sw[d * 8 + jq];
            acc = fmaf(w4.x, x[jq * 4 + 0], acc);
            acc = fmaf(w4.y, x[jq * 4 + 1], acc);
            acc = fmaf(w4.z, x[jq * 4 + 2], acc);
            acc = fmaf(w4.w, x[jq * 4 + 3], acc);
        }
        out[d] = acc;
    }
    float4* op = (float4*)(O + ((size_t)b * NN + i) * CC + h * DK);
#pragma unroll
    for (int r = 0; r < 8; r++)
        op[r] = make_float4(out[r * 4], out[r * 4 + 1], out[r * 4 + 2], out[r * 4 + 3]);
}

// ---------------- 3) sparse masked attention (warp per query, ALL heads) ----
// lane = (h = lane>>2, c = lane&3); each lane owns 8 dims of head h.
// Neighbor index shared across heads; full 1KB k/v rows loaded coalesced.
// Two independent online-softmax streams (even/odd neighbors) per head,
// merged locally at the end (no shuffles needed for the merge).
__global__ __launch_bounds__(256) void attn_kernel() {
    int warp = threadIdx.x >> 5, lane = threadIdx.x & 31;
    int c = lane & 3;
    int gi = blockIdx.x * 8 + warp;          // b*NN + i
    if (gi >= BS * NN) return;
    int b = gi / NN;

    int cnt = g_cnt[gi];
    int off = (lane >> 2) * DK + c * 8;      // this lane's 8-dim slice
    const float* vbase = g_v + (size_t)b * NN * CC;
    float* valp = g_val + (size_t)gi * CC + off;
    int i_local = gi - b * NN;

    if (cnt == 0) {   // has_nb == 0 fallback: val = v
        const float4* vr = (const float4*)(vbase + (size_t)i_local * CC + off);
        float4 v0 = vr[0], v1 = vr[1];
        ((float4*)valp)[0] = v0;
        ((float4*)valp)[1] = v1;
        return;
    }

    const float4* qp = (const float4*)(g_q + (size_t)gi * CC + off);
    float4 qa = qp[0], qb = qp[1];
    const unsigned short* nb = g_nbr + (size_t)gi * NN;
    const float* kbase = g_k + (size_t)b * NN * CC;
    int cm1 = cnt - 1;

    // reference: max_val = max(attn * mask) -> masked zeros participate in max
    float minit = (cnt < NN) ? 0.0f : -INFINITY;
    float mA = minit, mB = minit, lA = 0.f, lB = 0.f;
    float4 oAa = {0,0,0,0}, oAb = {0,0,0,0}, oBa = {0,0,0,0}, oBb = {0,0,0,0};

    // prologue: neighbors 0,1 (clamped -> always-valid loads)
    int j0 = nb[0], j1 = nb[min(1, cm1)];
    const float4* kp0 = (const float4*)(kbase + (size_t)j0 * CC + off);
    const float4* vp0 = (const float4*)(vbase + (size_t)j0 * CC + off);
    const float4* kp1 = (const float4*)(kbase + (size_t)j1 * CC + off);
    const float4* vp1 = (const float4*)(vbase + (size_t)j1 * CC + off);
    float4 kAa = kp0[0], kAb = kp0[1], vAa = vp0[0], vAb = vp0[1];
    float4 kBa = kp1[0], kBb = kp1[1], vBa = vp1[0], vBb = vp1[1];

    for (int t = 0; t < cnt; t += 2) {
        // prefetch neighbors t+2, t+3
        int jn0 = nb[min(t + 2, cm1)], jn1 = nb[min(t + 3, cm1)];
        const float4* kn0 = (const float4*)(kbase + (size_t)jn0 * CC + off);
        const float4* vn0 = (const float4*)(vbase + (size_t)jn0 * CC + off);
        const float4* kn1 = (const float4*)(kbase + (size_t)jn1 * CC + off);
        const float4* vn1 = (const float4*)(vbase + (size_t)jn1 * CC + off);
        float4 nkAa = kn0[0], nkAb = kn0[1], nvAa = vn0[0], nvAb = vn0[1];
        float4 nkBa = kn1[0], nkBb = kn1[1], nvBa = vn1[0], nvBb = vn1[1];

        // stream A (t < cnt always)
        float sA = qa.x * kAa.x + qa.y * kAa.y + qa.z * kAa.z + qa.w * kAa.w
                 + qb.x * kAb.x + qb.y * kAb.y + qb.z * kAb.z + qb.w * kAb.w;
        sA += __shfl_xor_sync(0xffffffffu, sA, 1);
        sA += __shfl_xor_sync(0xffffffffu, sA, 2);
        float mnA = fmaxf(mA, sA);
        float scA = __expf(mA - mnA);
        float pA = __expf(sA - mnA);
        lA = lA * scA + pA;
        oAa.x = fmaf(pA, vAa.x, oAa.x * scA); oAa.y = fmaf(pA, vAa.y, oAa.y * scA);
        oAa.z = fmaf(pA, vAa.z, oAa.z * scA); oAa.w = fmaf(pA, vAa.w, oAa.w * scA);
        oAb.x = fmaf(pA, vAb.x, oAb.x * scA); oAb.y = fmaf(pA, vAb.y, oAb.y * scA);
        oAb.z = fmaf(pA, vAb.z, oAb.z * scA); oAb.w = fmaf(pA, vAb.w, oAb.w * scA);
        mA = mnA;

        // stream B (t+1 may be past the end)
        float sB = qa.x * kBa.x + qa.y * kBa.y + qa.z * kBa.z + qa.w * kBa.w
                 + qb.x * kBb.x + qb.y * kBb.y + qb.z * kBb.z + qb.w * kBb.w;
        sB += __shfl_xor_sync(0xffffffffu, sB, 1);
        sB += __shfl_xor_sync(0xffffffffu, sB, 2);
        if (t + 1 >= cnt) sB = -INFINITY;
        float mnB = fmaxf(mB, sB);
        float scB = __expf(mB - mnB);
        float pB = __expf(sB - mnB);          // exp(-inf)=0 for padding
        lB = lB * scB + pB;
        oBa.x = fmaf(pB, vBa.x, oBa.x * scB); oBa.y = fmaf(pB, vBa.y, oBa.y * scB);
        oBa.z = fmaf(pB, vBa.z, oBa.z * scB); oBa.w = fmaf(pB, vBa.w, oBa.w * scB);
        oBb.x = fmaf(pB, vBb.x, oBb.x * scB); oBb.y = fmaf(pB, vBb.y, oBb.y * scB);
        oBb.z = fmaf(pB, vBb.z, oBb.z * scB); oBb.w = fmaf(pB, vBb.w, oBb.w * scB);
        mB = mnB;

        kAa = nkAa; kAb = nkAb; vAa = nvAa; vAb = nvAb;
        kBa = nkBa; kBb = nkBb; vBa = nvBa; vBb = nvBb;
    }

    // merge the two streams locally (no shuffles: 4 lanes of a head hold
    // identical m/l and disjoint dims of o)
    float m = fmaxf(mA, mB);
    float eA = __expf(mA - m), eB = __expf(mB - m);
    float l = lA * eA + lB * eB;
    float inv = 1.0f / (l + 1e-8f);
    float4 ra, rb;
    ra.x = (oAa.x * eA + oBa.x * eB) * inv; ra.y = (oAa.y * eA + oBa.y * eB) * inv;
    ra.z = (oAa.z * eA + oBa.z * eB) * inv; ra.w = (oAa.w * eA + oBa.w * eB) * inv;
    rb.x = (oAb.x * eA + oBb.x * eB) * inv; rb.y = (oAb.y * eA + oBb.y * eB) * inv;
    rb.z = (oAb.z * eA + oBb.z * eB) * inv; rb.w = (oAb.w * eA + oBb.w * eB) * inv;
    ((float4*)valp)[0] = ra;
    ((float4*)valp)[1] = rb;
}

// ---------------- 4) output projection  out = Wp @ val + b ------------------
// 128(co) x 64(i) tile, 128 threads, 8x8 per thread, KC=32 chunks with
// register-prefetch double buffering.
#define PCO 128
#define PII 64
#define PKC 32
__global__ __launch_bounds__(128) void proj_kernel(const float* __restrict__ wp,
                                                   const float* __restrict__ bp,
                                                   float* __restrict__ out) {
    __shared__ float Ws[PKC][PCO + 4];   // [ci][co]
    __shared__ float Vs[PKC][PII + 4];   // [ci][i]
    int b = blockIdx.z;
    int coT = blockIdx.y * PCO;
    int iT = blockIdx.x * PII;
    int t = threadIdx.x;
    int tx = t & 7;                    // i group: tx*4 and tx*4+32
    int ty = t >> 3;                   // co group (0..15): ty*4 and ty*4+64
    int ci4 = (t & 7) * 4;             // load column group (0..28)
    int r0 = t >> 3;                   // load row base (0..15)

    float4 wpre[8], vpre[4];
#pragma unroll
    for (int p = 0; p < 8; p++)
        wpre[p] = *(const float4*)&wp[(size_t)(coT + r0 + p * 16) * CC + ci4];
#pragma unroll
    for (int p = 0; p < 4; p++) {
        int gi = iT + r0 + p * 16;
        vpre[p] = (gi < NN) ? *(const float4*)&g_val[((size_t)b * NN + gi) * CC + ci4]
                            : make_float4(0.f, 0.f, 0.f, 0.f);
    }

    float acc[8][8] = {};

    for (int kc = 0; kc < CC; kc += PKC) {
#pragma unroll
        for (int p = 0; p < 8; p++) {
            int r = r0 + p * 16;
            Ws[ci4 + 0][r] = wpre[p].x; Ws[ci4 + 1][r] = wpre[p].y;
            Ws[ci4 + 2][r] = wpre[p].z; Ws[ci4 + 3][r] = wpre[p].w;
        }
#pragma unroll
        for (int p = 0; p < 4; p++) {
            int io = r0 + p * 16;
            Vs[ci4 + 0][io] = vpre[p].x; Vs[ci4 + 1][io] = vpre[p].y;
            Vs[ci4 + 2][io] = vpre[p].z; Vs[ci4 + 3][io] = vpre[p].w;
        }
        __syncthreads();

        if (kc + PKC < CC) {
            int kcn = kc + PKC;
#pragma unroll
            for (int p = 0; p < 8; p++)
                wpre[p] = *(const float4*)&wp[(size_t)(coT + r0 + p * 16) * CC + kcn + ci4];
#pragma unroll
            for (int p = 0; p < 4; p++) {
                int gi = iT + r0 + p * 16;
                vpre[p] = (gi < NN) ? *(const float4*)&g_val[((size_t)b * NN + gi) * CC + kcn + ci4]
                                    : make_float4(0.f, 0.f, 0.f, 0.f);
            }
        }

#pragma unroll 8
        for (int ci = 0; ci < PKC; ci++) {
            float4 w0 = *(const float4*)&Ws[ci][ty * 4];
            float4 w1 = *(const float4*)&Ws[ci][64 + ty * 4];
            float4 v0 = *(const float4*)&Vs[ci][tx * 4];
            float4 v1 = *(const float4*)&Vs[ci][32 + tx * 4];
            float wr[8] = {w0.x, w0.y, w0.z, w0.w, w1.x, w1.y, w1.z, w1.w};
            float vr[8] = {v0.x, v0.y, v0.z, v0.w, v1.x, v1.y, v1.z, v1.w};
#pragma unroll
            for (int a = 0; a < 8; a++)
#pragma unroll
                for (int e = 0; e < 8; e++)
                    acc[a][e] = fmaf(wr[a], vr[e], acc[a][e]);
        }
        __syncthreads();
    }

#pragma unroll
    for (int a = 0; a < 8; a++) {
        int co = coT + (a < 4 ? (ty * 4 + a) : (64 + ty * 4 + (a - 4)));
        float bias = bp[co];
#pragma unroll
        for (int half = 0; half < 2; half++) {
            int gi = iT + (half == 0 ? tx * 4 : 32 + tx * 4);
            int e0 = half * 4;
            if (gi < NN) {   // NN % 4 == 0, whole float4 valid
                float4 r = make_float4(acc[a][e0 + 0] + bias, acc[a][e0 + 1] + bias,
                                       acc[a][e0 + 2] + bias, acc[a][e0 + 3] + bias);
                *(float4*)&out[((size_t)b * CC + co) * NN + gi] = r;
            }
        }
    }
}

// ---------------- launch ----------------------------------------------------
extern "C" void kernel_launch(void* const* d_in, const int* in_sizes, int n_in,
                              void* d_out, int out_size) {
    const float* queries = (const float*)d_in[0];
    const float* keys    = (const float*)d_in[1];
    const float* values  = (const float*)d_in[2];
    const float* boxes   = (const float*)d_in[3];
    const float* curmask = (const float*)d_in[4];
    const float* wq      = (const float*)d_in[5];
    const float* wk      = (const float*)d_in[6];
    const float* wv      = (const float*)d_in[7];
    const float* w_proj  = (const float*)d_in[8];
    const float* b_proj  = (const float*)d_in[9];
    float* out = (float*)d_out;

    mask_kernel<<<dim3(188, BS), 256>>>(boxes, curmask);
    qkv_kernel<<<dim3(6, BS * HH, 3), 256>>>(queries, keys, values, wq, wk, wv);
    attn_kernel<<<dim3((BS * NN + 7) / 8), 256>>>();
    proj_kernel<<<dim3((NN + PII - 1) / PII, CC / PCO, BS), 128>>>(w_proj, b_proj, out);
}

// round 5
// speedup vs baseline: 1.1732x; 1.0365x over previous
#include <cuda_runtime.h>
#include <math.h>

#define BS 8
#define CC 256
#define NN 1500
#define HH 8
#define DK 32

typedef unsigned long long ull;

// ---------------- f32x2 packed helpers (Blackwell) ---------------------------
__device__ __forceinline__ ull pk2(float lo, float hi) {
    ull r;
    asm("mov.b64 %0, {%1, %2};" : "=l"(r)
        : "r"(__float_as_uint(lo)), "r"(__float_as_uint(hi)));
    return r;
}
__device__ __forceinline__ ull fma2(ull a, ull b, ull c) {
    ull d;
    asm("fma.rn.f32x2 %0, %1, %2, %3;" : "=l"(d) : "l"(a), "l"(b), "l"(c));
    return d;
}
__device__ __forceinline__ void unpk2(ull v, float& lo, float& hi) {
    unsigned ulo, uhi;
    asm("mov.b64 {%0, %1}, %2;" : "=r"(ulo), "=r"(uhi) : "l"(v));
    lo = __uint_as_float(ulo); hi = __uint_as_float(uhi);
}

// ---------------- scratch (static device globals; no allocs) ----------------
// q/k/v stored head-interleaved: [b][n][h*DK]  (256 floats per token row)
__device__ float g_q[(size_t)BS * NN * CC];
__device__ float g_k[(size_t)BS * NN * CC];
__device__ float g_v[(size_t)BS * NN * CC];
__device__ float g_val[(size_t)BS * NN * CC];              // [b][n][c]
__device__ unsigned short g_nbr[(size_t)BS * NN * NN];     // per-row neighbor j lists
__device__ int g_cnt[BS * NN];
__device__ int g_perm[BS * NN];                            // spatial-sorted order

// ---------------- 0) spatial counting sort (per batch) ----------------------
// 8x8 grid on (cx, cy). perm[rank] = original index. Order within a cell is
// nondeterministic but the per-query computation is order-independent, so the
// kernel output is deterministic.
__global__ __launch_bounds__(256) void sort_kernel(const float* __restrict__ boxes) {
    __shared__ int hist[64], offs[64];
    int b = blockIdx.x;
    int t = threadIdx.x;
    if (t < 64) hist[t] = 0;
    __syncthreads();
    const float4* bb = (const float4*)(boxes + (size_t)b * NN * 4);
    for (int n = t; n < NN; n += 256) {
        float4 bx = bb[n];
        int kx = min(7, max(0, (int)(bx.x * 8.0f)));
        int ky = min(7, max(0, (int)(bx.y * 8.0f)));
        atomicAdd(&hist[kx * 8 + ky], 1);
    }
    __syncthreads();
    if (t == 0) {
        int run = 0;
        for (int k = 0; k < 64; k++) { offs[k] = run; run += hist[k]; }
    }
    __syncthreads();
    for (int n = t; n < NN; n += 256) {
        float4 bx = bb[n];
        int kx = min(7, max(0, (int)(bx.x * 8.0f)));
        int ky = min(7, max(0, (int)(bx.y * 8.0f)));
        int pos = atomicAdd(&offs[kx * 8 + ky], 1);
        g_perm[b * NN + pos] = n;
    }
}

// ---------------- 1) mask + neighbor-list build (per batch, head-shared) ----
__global__ __launch_bounds__(256) void mask_kernel(const float* __restrict__ boxes,
                                                   const float* __restrict__ cm) {
    __shared__ float sx1[NN], sy1[NN], sx2[NN], sy2[NN], sa[NN], scm[NN];
    int b = blockIdx.y;
    const float4* bb = (const float4*)(boxes + (size_t)b * NN * 4);
    for (int idx = threadIdx.x; idx < NN; idx += blockDim.x) {
        float4 bx = bb[idx];                  // cx, cy, w, h
        float x1 = bx.x - 0.5f * bx.z;
        float x2 = bx.x + 0.5f * bx.z;
        float y1 = bx.y - 0.5f * bx.w;
        float y2 = bx.y + 0.5f * bx.w;
        sx1[idx] = x1; sx2[idx] = x2; sy1[idx] = y1; sy2[idx] = y2;
        sa[idx] = (x2 - x1) * (y2 - y1);
        scm[idx] = cm[(size_t)b * NN + idx];
    }
    __syncthreads();

    int warp = threadIdx.x >> 5, lane = threadIdx.x & 31;
    int i = blockIdx.x * 8 + warp;
    if (i >= NN) return;
    float x1i = sx1[i], x2i = sx2[i], y1i = sy1[i], y2i = sy2[i];
    float ai = sa[i], cmi = scm[i];
    unsigned short* out = g_nbr + ((size_t)b * NN + i) * NN;
    int cnt = 0;
    for (int jb = 0; jb < NN; jb += 32) {
        int j = jb + lane;
        bool nb = false;
        if (j < NN) {
            float ltx = fmaxf(x1i, sx1[j]);
            float lty = fmaxf(y1i, sy1[j]);
            float rbx = fminf(x2i, sx2[j]);
            float rby = fminf(y2i, sy2[j]);
            float iw = fmaxf(rbx - ltx, 0.0f);
            float ih = fmaxf(rby - lty, 0.0f);
            float inter = iw * ih;
            float uni = (ai + sa[j]) - inter;
            float prod = cmi * scm[j];
            if (prod == 1.0f) {
                // exact predicate for fl_RN(inter/uni) > 0.5 without dividing:
                // true  <=>  inter/uni > 0.5 + 2^-25  (RN ties-even boundary)
                float i2 = inter + inter;
                if (i2 > uni * 1.00001f) nb = true;
                else if (i2 < uni * 0.99999f) nb = false;
                else nb = ((double)inter >
                           (double)uni * 0.5000000298023223876953125);
                // uni==0 -> all compares false -> matches NaN>0.5 == false
            } else {
                float iou = __fdiv_rn(inter, uni);
                nb = (iou * prod) > 0.5f;
            }
        }
        unsigned bal = __ballot_sync(0xffffffffu, nb);
        int pos = cnt + __popc(bal & ((1u << lane) - 1u));
        if (nb) out[pos] = (unsigned short)j;
        cnt += __popc(bal);
    }
    if (lane == 0) g_cnt[b * NN + i] = cnt;
}

// ---------------- 2) QKV head projections (head-interleaved output) ---------
__global__ __launch_bounds__(256) void qkv_kernel(const float* __restrict__ qin,
                                                  const float* __restrict__ kin,
                                                  const float* __restrict__ vin,
                                                  const float* __restrict__ wq,
                                                  const float* __restrict__ wk,
                                                  const float* __restrict__ wv) {
    __shared__ float4 sw[256];   // 32x32 weight matrix for this (mat, h)
    int mat = blockIdx.z;
    int bh = blockIdx.y;
    int b = bh >> 3, h = bh & 7;
    const float* W = (mat == 0 ? wq : (mat == 1 ? wk : wv)) + h * DK * DK;
    const float* X = (mat == 0 ? qin : (mat == 1 ? kin : vin));
    float* O = (mat == 0 ? g_q : (mat == 1 ? g_k : g_v));
    sw[threadIdx.x] = ((const float4*)W)[threadIdx.x];
    __syncthreads();

    int i = blockIdx.x * 256 + threadIdx.x;
    if (i >= NN) return;
    float x[DK];
    const float* xp = X + ((size_t)b * CC + h * DK) * NN + i;
#pragma unroll
    for (int j = 0; j < DK; j++) x[j] = xp[(size_t)j * NN];

    float out[DK];
#pragma unroll
    for (int d = 0; d < DK; d++) {
        float acc = 0.0f;
#pragma unroll
        for (int jq = 0; jq < 8; jq++) {
            float4 w4 = sw[d * 8 + jq];
            acc = fmaf(w4.x, x[jq * 4 + 0], acc);
            acc = fmaf(w4.y, x[jq * 4 + 1], acc);
            acc = fmaf(w4.z, x[jq * 4 + 2], acc);
            acc = fmaf(w4.w, x[jq * 4 + 3], acc);
        }
        out[d] = acc;
    }
    float4* op = (float4*)(O + ((size_t)b * NN + i) * CC + h * DK);
#pragma unroll
    for (int r = 0; r < 8; r++)
        op[r] = make_float4(out[r * 4], out[r * 4 + 1], out[r * 4 + 2], out[r * 4 + 3]);
}

// ---------------- 3) sparse masked attention (warp per query, ALL heads) ----
// Block handles 8 spatially-sorted-adjacent queries (via g_perm) so the
// warps' neighbor k/v rows overlap and hit L1 instead of re-pulling L2.
__global__ __launch_bounds__(256) void attn_kernel() {
    int warp = threadIdx.x >> 5, lane = threadIdx.x & 31;
    int c = lane & 3;
    int gs = blockIdx.x * 8 + warp;          // sorted rank within b*NN
    if (gs >= BS * NN) return;
    int b = gs / NN;
    int gi = b * NN + g_perm[gs];            // actual b*NN + i

    int cnt = g_cnt[gi];
    int off = (lane >> 2) * DK + c * 8;      // this lane's 8-dim slice
    const float* vbase = g_v + (size_t)b * NN * CC;
    float* valp = g_val + (size_t)gi * CC + off;
    int i_local = gi - b * NN;

    if (cnt == 0) {   // has_nb == 0 fallback: val = v
        const float4* vr = (const float4*)(vbase + (size_t)i_local * CC + off);
        float4 v0 = vr[0], v1 = vr[1];
        ((float4*)valp)[0] = v0;
        ((float4*)valp)[1] = v1;
        return;
    }

    const float4* qp = (const float4*)(g_q + (size_t)gi * CC + off);
    float4 qa = qp[0], qb = qp[1];
    const unsigned short* nb = g_nbr + (size_t)gi * NN;
    const float* kbase = g_k + (size_t)b * NN * CC;
    int cm1 = cnt - 1;

    // reference: max_val = max(attn * mask) -> masked zeros participate in max
    float minit = (cnt < NN) ? 0.0f : -INFINITY;
    float mA = minit, mB = minit, lA = 0.f, lB = 0.f;
    float4 oAa = {0,0,0,0}, oAb = {0,0,0,0}, oBa = {0,0,0,0}, oBb = {0,0,0,0};

    // prologue: neighbors 0,1 (clamped -> always-valid loads)
    int j0 = nb[0], j1 = nb[min(1, cm1)];
    const float4* kp0 = (const float4*)(kbase + (size_t)j0 * CC + off);
    const float4* vp0 = (const float4*)(vbase + (size_t)j0 * CC + off);
    const float4* kp1 = (const float4*)(kbase + (size_t)j1 * CC + off);
    const float4* vp1 = (const float4*)(vbase + (size_t)j1 * CC + off);
    float4 kAa = kp0[0], kAb = kp0[1], vAa = vp0[0], vAb = vp0[1];
    float4 kBa = kp1[0], kBb = kp1[1], vBa = vp1[0], vBb = vp1[1];

    for (int t = 0; t < cnt; t += 2) {
        // prefetch neighbors t+2, t+3
        int jn0 = nb[min(t + 2, cm1)], jn1 = nb[min(t + 3, cm1)];
        const float4* kn0 = (const float4*)(kbase + (size_t)jn0 * CC + off);
        const float4* vn0 = (const float4*)(vbase + (size_t)jn0 * CC + off);
        const float4* kn1 = (const float4*)(kbase + (size_t)jn1 * CC + off);
        const float4* vn1 = (const float4*)(vbase + (size_t)jn1 * CC + off);
        float4 nkAa = kn0[0], nkAb = kn0[1], nvAa = vn0[0], nvAb = vn0[1];
        float4 nkBa = kn1[0], nkBb = kn1[1], nvBa = vn1[0], nvBb = vn1[1];

        // stream A (t < cnt always)
        float sA = qa.x * kAa.x + qa.y * kAa.y + qa.z * kAa.z + qa.w * kAa.w
                 + qb.x * kAb.x + qb.y * kAb.y + qb.z * kAb.z + qb.w * kAb.w;
        sA += __shfl_xor_sync(0xffffffffu, sA, 1);
        sA += __shfl_xor_sync(0xffffffffu, sA, 2);
        float mnA = fmaxf(mA, sA);
        float scA = __expf(mA - mnA);
        float pA = __expf(sA - mnA);
        lA = lA * scA + pA;
        oAa.x = fmaf(pA, vAa.x, oAa.x * scA); oAa.y = fmaf(pA, vAa.y, oAa.y * scA);
        oAa.z = fmaf(pA, vAa.z, oAa.z * scA); oAa.w = fmaf(pA, vAa.w, oAa.w * scA);
        oAb.x = fmaf(pA, vAb.x, oAb.x * scA); oAb.y = fmaf(pA, vAb.y, oAb.y * scA);
        oAb.z = fmaf(pA, vAb.z, oAb.z * scA); oAb.w = fmaf(pA, vAb.w, oAb.w * scA);
        mA = mnA;

        // stream B (t+1 may be past the end)
        float sB = qa.x * kBa.x + qa.y * kBa.y + qa.z * kBa.z + qa.w * kBa.w
                 + qb.x * kBb.x + qb.y * kBb.y + qb.z * kBb.z + qb.w * kBb.w;
        sB += __shfl_xor_sync(0xffffffffu, sB, 1);
        sB += __shfl_xor_sync(0xffffffffu, sB, 2);
        if (t + 1 >= cnt) sB = -INFINITY;
        float mnB = fmaxf(mB, sB);
        float scB = __expf(mB - mnB);
        float pB = __expf(sB - mnB);          // exp(-inf)=0 for padding
        lB = lB * scB + pB;
        oBa.x = fmaf(pB, vBa.x, oBa.x * scB); oBa.y = fmaf(pB, vBa.y, oBa.y * scB);
        oBa.z = fmaf(pB, vBa.z, oBa.z * scB); oBa.w = fmaf(pB, vBa.w, oBa.w * scB);
        oBb.x = fmaf(pB, vBb.x, oBb.x * scB); oBb.y = fmaf(pB, vBb.y, oBb.y * scB);
        oBb.z = fmaf(pB, vBb.z, oBb.z * scB); oBb.w = fmaf(pB, vBb.w, oBb.w * scB);
        mB = mnB;

        kAa = nkAa; kAb = nkAb; vAa = nvAa; vAb = nvAb;
        kBa = nkBa; kBb = nkBb; vBa = nvBa; vBb = nvBb;
    }

    // merge the two streams locally
    float m = fmaxf(mA, mB);
    float eA = __expf(mA - m), eB = __expf(mB - m);
    float l = lA * eA + lB * eB;
    float inv = 1.0f / (l + 1e-8f);
    float4 ra, rb;
    ra.x = (oAa.x * eA + oBa.x * eB) * inv; ra.y = (oAa.y * eA + oBa.y * eB) * inv;
    ra.z = (oAa.z * eA + oBa.z * eB) * inv; ra.w = (oAa.w * eA + oBa.w * eB) * inv;
    rb.x = (oAb.x * eA + oBb.x * eB) * inv; rb.y = (oAb.y * eA + oBb.y * eB) * inv;
    rb.z = (oAb.z * eA + oBb.z * eB) * inv; rb.w = (oAb.w * eA + oBb.w * eB) * inv;
    ((float4*)valp)[0] = ra;
    ((float4*)valp)[1] = rb;
}

// ---------------- 4) output projection  out = Wp @ val + b ------------------
// 128(co) x 64(i) tile, 128 threads, 8x8 per thread. Weights stored in smem
// as duplicated (w,w) f32x2 pairs; inner loop is pure LDS.128 + FFMA2
// (fma.rn.f32x2), doubling flops per instruction vs scalar FFMA.
#define PCO 128
#define PII 64
#define PKC 32
__global__ __launch_bounds__(128) void proj_kernel(const float* __restrict__ wp,
                                                   const float* __restrict__ bp,
                                                   float* __restrict__ out) {
    __shared__ ull Ws2[PKC][PCO + 2];    // [ci][co] duplicated pairs
    __shared__ float Vs[PKC][PII + 4];   // [ci][i]
    int b = blockIdx.z;
    int coT = blockIdx.y * PCO;
    int iT = blockIdx.x * PII;
    int t = threadIdx.x;
    int tx = t & 7;                    // i group: tx*4 and tx*4+32
    int ty = t >> 3;                   // co group (0..15): ty*4 and ty*4+64
    int ci4 = (t & 7) * 4;             // load column group (0..28)
    int r0 = t >> 3;                   // load row base (0..15)

    float4 wpre[8], vpre[4];
#pragma unroll
    for (int p = 0; p < 8; p++)
        wpre[p] = *(const float4*)&wp[(size_t)(coT + r0 + p * 16) * CC + ci4];
#pragma unroll
    for (int p = 0; p < 4; p++) {
        int gi = iT + r0 + p * 16;
        vpre[p] = (gi < NN) ? *(const float4*)&g_val[((size_t)b * NN + gi) * CC + ci4]
                            : make_float4(0.f, 0.f, 0.f, 0.f);
    }

    ull acc2[8][4];
#pragma unroll
    for (int a = 0; a < 8; a++)
#pragma unroll
        for (int e = 0; e < 4; e++) acc2[a][e] = 0ull;   // (0.f, 0.f)

    for (int kc = 0; kc < CC; kc += PKC) {
#pragma unroll
        for (int p = 0; p < 8; p++) {
            int r = r0 + p * 16;
            Ws2[ci4 + 0][r] = pk2(wpre[p].x, wpre[p].x);
            Ws2[ci4 + 1][r] = pk2(wpre[p].y, wpre[p].y);
            Ws2[ci4 + 2][r] = pk2(wpre[p].z, wpre[p].z);
            Ws2[ci4 + 3][r] = pk2(wpre[p].w, wpre[p].w);
        }
#pragma unroll
        for (int p = 0; p < 4; p++) {
            int io = r0 + p * 16;
            Vs[ci4 + 0][io] = vpre[p].x; Vs[ci4 + 1][io] = vpre[p].y;
            Vs[ci4 + 2][io] = vpre[p].z; Vs[ci4 + 3][io] = vpre[p].w;
        }
        __syncthreads();

        if (kc + PKC < CC) {
            int kcn = kc + PKC;
#pragma unroll
            for (int p = 0; p < 8; p++)
                wpre[p] = *(const float4*)&wp[(size_t)(coT + r0 + p * 16) * CC + kcn + ci4];
#pragma unroll
            for (int p = 0; p < 4; p++) {
                int gi = iT + r0 + p * 16;
                vpre[p] = (gi < NN) ? *(const float4*)&g_val[((size_t)b * NN + gi) * CC + kcn + ci4]
                                    : make_float4(0.f, 0.f, 0.f, 0.f);
            }
        }

#pragma unroll 8
        for (int ci = 0; ci < PKC; ci++) {
            ulonglong2 wA = *(const ulonglong2*)&Ws2[ci][ty * 4];
            ulonglong2 wB = *(const ulonglong2*)&Ws2[ci][ty * 4 + 2];
            ulonglong2 wC = *(const ulonglong2*)&Ws2[ci][64 + ty * 4];
            ulonglong2 wD = *(const ulonglong2*)&Ws2[ci][64 + ty * 4 + 2];
            ulonglong2 vA = *(const ulonglong2*)&Vs[ci][tx * 4];
            ulonglong2 vB = *(const ulonglong2*)&Vs[ci][32 + tx * 4];
            ull wr[8] = {wA.x, wA.y, wB.x, wB.y, wC.x, wC.y, wD.x, wD.y};
            ull vr[4] = {vA.x, vA.y, vB.x, vB.y};
#pragma unroll
            for (int a = 0; a < 8; a++)
#pragma unroll
                for (int e = 0; e < 4; e++)
                    acc2[a][e] = fma2(wr[a], vr[e], acc2[a][e]);
        }
        __syncthreads();
    }

    // unpack to scalar accumulators
    float acc[8][8];
#pragma unroll
    for (int a = 0; a < 8; a++)
#pragma unroll
        for (int e = 0; e < 4; e++)
            unpk2(acc2[a][e], acc[a][2 * e], acc[a][2 * e + 1]);

#pragma unroll
    for (int a = 0; a < 8; a++) {
        int co = coT + (a < 4 ? (ty * 4 + a) : (64 + ty * 4 + (a - 4)));
        float bias = bp[co];
#pragma unroll
        for (int half = 0; half < 2; half++) {
            int gi = iT + (half == 0 ? tx * 4 : 32 + tx * 4);
            int e0 = half * 4;
            if (gi < NN) {   // NN % 4 == 0, whole float4 valid
                float4 r = make_float4(acc[a][e0 + 0] + bias, acc[a][e0 + 1] + bias,
                                       acc[a][e0 + 2] + bias, acc[a][e0 + 3] + bias);
                *(float4*)&out[((size_t)b * CC + co) * NN + gi] = r;
            }
        }
    }
}

// ---------------- launch ----------------------------------------------------
extern "C" void kernel_launch(void* const* d_in, const int* in_sizes, int n_in,
                              void* d_out, int out_size) {
    const float* queries = (const float*)d_in[0];
    const float* keys    = (const float*)d_in[1];
    const float* values  = (const float*)d_in[2];
    const float* boxes   = (const float*)d_in[3];
    const float* curmask = (const float*)d_in[4];
    const float* wq      = (const float*)d_in[5];
    const float* wk      = (const float*)d_in[6];
    const float* wv      = (const float*)d_in[7];
    const float* w_proj  = (const float*)d_in[8];
    const float* b_proj  = (const float*)d_in[9];
    float* out = (float*)d_out;

    sort_kernel<<<BS, 256>>>(boxes);
    mask_kernel<<<dim3(188, BS), 256>>>(boxes, curmask);
    qkv_kernel<<<dim3(6, BS * HH, 3), 256>>>(queries, keys, values, wq, wk, wv);
    attn_kernel<<<dim3((BS * NN + 7) / 8), 256>>>();
    proj_kernel<<<dim3((NN + PII - 1) / PII, CC / PCO, BS), 128>>>(w_proj, b_proj, out);
}